// round 1
// baseline (speedup 1.0000x reference)
#include <cuda_runtime.h>
#include <stdint.h>

#define OUTF 8192
#define INF  8192
#define GROUPS 256            // groups of 32 in-features (3 packed words each)
#define KS 32                 // split-K factor
#define GPB (GROUPS / KS)     // 8 groups per block
#define TPB 128
#define COLS_PER_THREAD 4
#define COLS_PER_BLOCK (TPB * COLS_PER_THREAD)   // 512
#define NCB (OUTF / COLS_PER_BLOCK)              // 16
#define ROWSTRIDE4 (OUTF / 4)                    // uint4 row stride

// split-K partial dot products: partial[k][n] = sum over K-slice k of x*q
__device__ float g_partial[KS * OUTF];

// exact int3 -> float via magic number (no I2F): 0x4B000000|v == 2^23 + v
__device__ __forceinline__ float dq3(unsigned v) {
    return __uint_as_float(0x4B000000u | v) - 8388608.0f;
}

// unpack one GPTQ int3 triple (32 values) for one column, accumulate x·q
__device__ __forceinline__ float unpack_col(unsigned w0, unsigned w1, unsigned w2,
                                            const float* __restrict__ xr, float acc) {
#pragma unroll
    for (int j = 0; j < 10; j++)
        acc = fmaf(xr[j], dq3((w0 >> (3 * j)) & 7u), acc);
    acc = fmaf(xr[10], dq3(((w0 >> 30) & 3u) | ((w1 & 1u) << 2)), acc);
#pragma unroll
    for (int j = 0; j < 10; j++)
        acc = fmaf(xr[11 + j], dq3((w1 >> (3 * j + 1)) & 7u), acc);
    acc = fmaf(xr[21], dq3(((w1 >> 31) & 1u) | ((w2 & 3u) << 1)), acc);
#pragma unroll
    for (int j = 0; j < 10; j++)
        acc = fmaf(xr[22 + j], dq3((w2 >> (3 * j + 2)) & 7u), acc);
    return acc;
}

__global__ __launch_bounds__(TPB)
void q3_dot_kernel(const float* __restrict__ x, const unsigned* __restrict__ qw) {
    __shared__ float xs[GPB * 32];

    const int tid = threadIdx.x;
    const int gbase = blockIdx.y * GPB;      // first group of this K-slice
    const int kbase = gbase * 32;            // first in-feature

    // stage this K-slice of x into shared
    for (int i = tid; i < GPB * 32; i += TPB) xs[i] = x[kbase + i];
    __syncthreads();

    const int c = blockIdx.x * COLS_PER_BLOCK + tid * COLS_PER_THREAD;
    const uint4* __restrict__ q4 = (const uint4*)qw;
    long base = (long)(gbase * 3) * ROWSTRIDE4 + (c >> 2);

    float a0 = 0.f, a1 = 0.f, a2 = 0.f, a3 = 0.f;

    // prologue load (group 0 of slice)
    uint4 cw0 = q4[base];
    uint4 cw1 = q4[base + ROWSTRIDE4];
    uint4 cw2 = q4[base + 2 * ROWSTRIDE4];

#pragma unroll 1
    for (int g = 0; g < GPB; g++) {
        uint4 nw0, nw1, nw2;
        if (g + 1 < GPB) {                   // prefetch next group while computing
            long nb = base + (long)(3 * (g + 1)) * ROWSTRIDE4;
            nw0 = q4[nb];
            nw1 = q4[nb + ROWSTRIDE4];
            nw2 = q4[nb + 2 * ROWSTRIDE4];
        }
        // pull this group's 32 x values into registers (broadcast LDS, reused 4x)
        float xr[32];
        const float* xp = &xs[g * 32];
#pragma unroll
        for (int j = 0; j < 32; j++) xr[j] = xp[j];

        a0 = unpack_col(cw0.x, cw1.x, cw2.x, xr, a0);
        a1 = unpack_col(cw0.y, cw1.y, cw2.y, xr, a1);
        a2 = unpack_col(cw0.z, cw1.z, cw2.z, xr, a2);
        a3 = unpack_col(cw0.w, cw1.w, cw2.w, xr, a3);

        cw0 = nw0; cw1 = nw1; cw2 = nw2;
    }

    float4 o = make_float4(a0, a1, a2, a3);
    *(float4*)&g_partial[blockIdx.y * OUTF + c] = o;
}

__global__ __launch_bounds__(256)
void q3_reduce_kernel(const float* __restrict__ x,
                      const float* __restrict__ scales,
                      const float* __restrict__ zeros,
                      const float* __restrict__ bias,
                      float* __restrict__ y) {
    __shared__ float red[256];
    const int tid = threadIdx.x;

    // deterministic block-wide sum of x (same value in every block)
    float s = 0.f;
    for (int i = tid; i < INF; i += 256) s += x[i];
    red[tid] = s;
    __syncthreads();
#pragma unroll
    for (int off = 128; off > 0; off >>= 1) {
        if (tid < off) red[tid] += red[tid + off];
        __syncthreads();
    }
    const float sumx = red[0];

    const int n = blockIdx.x * 256 + tid;
    float acc = 0.f;
#pragma unroll
    for (int k = 0; k < KS; k++) acc += g_partial[k * OUTF + n];

    y[n] = scales[n] * acc - zeros[n] * sumx + bias[n];
}

extern "C" void kernel_launch(void* const* d_in, const int* in_sizes, int n_in,
                              void* d_out, int out_size) {
    const float*    x      = (const float*)d_in[0];
    const unsigned* qw     = (const unsigned*)d_in[1];   // int32 bits -> uint32
    const float*    scales = (const float*)d_in[2];
    const float*    zeros  = (const float*)d_in[3];
    const float*    bias   = (const float*)d_in[4];
    float*          y      = (float*)d_out;

    dim3 grid(NCB, KS);
    q3_dot_kernel<<<grid, TPB>>>(x, qw);
    q3_reduce_kernel<<<OUTF / 256, 256>>>(x, scales, zeros, bias, y);
}